// round 1
// baseline (speedup 1.0000x reference)
#include <cuda_runtime.h>
#include <cstdint>

typedef unsigned long long ull;

// Problem dims (fixed by the dataset's setup_inputs)
constexpr int B   = 8;
constexpr int NC  = 19;
constexpr int HC  = 32;
constexpr int WC  = 64;
constexpr int CF  = 256;
constexpr int HF  = 128;
constexpr int WF  = 256;
constexpr int HID = 256;
constexpr int HW  = HF * WF;         // 32768
constexpr int NPTS = 2048;           // min(2048, HW/4)
constexpr int CIN1 = CF + NC;        // 275
constexpr int PPB  = 32;             // points per block in MLP kernel
constexpr int BLKS_PER_BATCH = NPTS / PPB;  // 64

// Scratch (static device memory — no allocation)
__device__ float g_unc[B * HW];
__device__ int   g_idx[B * NPTS];
__device__ int   g_tie[B * HW];

// ---------------------------------------------------------------------------
// f32x2 packed helpers
// ---------------------------------------------------------------------------
__device__ __forceinline__ ull fma2(ull a, ull b, ull c) {
    ull d;
    asm("fma.rn.f32x2 %0, %1, %2, %3;" : "=l"(d) : "l"(a), "l"(b), "l"(c));
    return d;
}
__device__ __forceinline__ ull pack2(float x) {
    ull r;
    asm("mov.b64 %0, {%1, %1};" : "=l"(r) : "f"(x));
    return r;
}
__device__ __forceinline__ void unpack2(ull v, float& x, float& y) {
    asm("mov.b64 {%0, %1}, %2;" : "=f"(x), "=f"(y) : "l"(v));
}

// ---------------------------------------------------------------------------
// Kernel A: bilinear upsample (align_corners) + uncertainty
// grid: B*HF blocks, WF threads
// ---------------------------------------------------------------------------
__global__ void __launch_bounds__(WF) upsample_unc_kernel(
    const float* __restrict__ coarse, float* __restrict__ out,
    float* __restrict__ unc)
{
    int w = threadIdx.x;
    int h = blockIdx.x % HF;
    int b = blockIdx.x / HF;

    float yf = (float)h * ((float)(HC - 1) / (float)(HF - 1));
    float xf = (float)w * ((float)(WC - 1) / (float)(WF - 1));
    int y0 = (int)floorf(yf); y0 = max(0, min(y0, HC - 1));
    int y1 = min(y0 + 1, HC - 1);
    float wy = yf - (float)y0;
    int x0 = (int)floorf(xf); x0 = max(0, min(x0, WC - 1));
    int x1 = min(x0 + 1, WC - 1);
    float wx = xf - (float)x0;

    const float* cb = coarse + (size_t)b * NC * HC * WC;
    float v[NC];
    float vmax = -3.4e38f;
#pragma unroll
    for (int c = 0; c < NC; c++) {
        const float* p = cb + c * HC * WC;
        float c00 = p[y0 * WC + x0], c10 = p[y1 * WC + x0];
        float c01 = p[y0 * WC + x1], c11 = p[y1 * WC + x1];
        float r0 = c00 * (1.f - wy) + c10 * wy;   // rows at x0
        float r1 = c01 * (1.f - wy) + c11 * wy;   // rows at x1
        float val = r0 * (1.f - wx) + r1 * wx;
        v[c] = val;
        vmax = fmaxf(vmax, val);
        out[((size_t)(b * NC + c) * HF + h) * WF + w] = val;
    }
    float s = 0.f;
#pragma unroll
    for (int c = 0; c < NC; c++) s += expf(v[c] - vmax);
    // max softmax prob = 1/s ; uncertainty = -maxprob
    unc[b * HW + h * WF + w] = -1.0f / s;
}

// ---------------------------------------------------------------------------
// Kernel B: exact top-NPTS per batch via 4x8-bit radix select.
// Ties at the threshold key are broken by smallest index (matches lax.top_k
// set semantics). grid: B blocks of 1024 threads.
// ---------------------------------------------------------------------------
__device__ __forceinline__ unsigned fkey(float f) {
    unsigned u = __float_as_uint(f);
    return (u & 0x80000000u) ? ~u : (u | 0x80000000u);  // monotone: larger f -> larger key
}

__global__ void __launch_bounds__(1024) topk_kernel() {
    int b = blockIdx.x;
    int tid = threadIdx.x;
    const float* u = g_unc + b * HW;

    __shared__ unsigned hist[256];
    __shared__ unsigned s_prefix;
    __shared__ unsigned s_mask;
    __shared__ int s_rem;
    __shared__ int cSel, cTie;

    if (tid == 0) { s_prefix = 0; s_mask = 0; s_rem = NPTS; cSel = 0; cTie = 0; }
    __syncthreads();

    for (int pass = 0; pass < 4; pass++) {
        int shift = (3 - pass) * 8;
        if (tid < 256) hist[tid] = 0;
        __syncthreads();
        unsigned mask = s_mask, pref = s_prefix;
        for (int i = tid; i < HW; i += 1024) {
            unsigned k = fkey(u[i]);
            if ((k & mask) == pref) atomicAdd(&hist[(k >> shift) & 255], 1u);
        }
        __syncthreads();
        if (tid == 0) {
            int need = s_rem;
            unsigned cum = 0;
            int sel = 0;
            for (int bin = 255; bin >= 0; bin--) {
                unsigned h = hist[bin];
                if (cum + h >= (unsigned)need) { sel = bin; s_rem = need - (int)cum; break; }
                cum += h;
            }
            s_prefix = pref | ((unsigned)sel << shift);
            s_mask = mask | (0xFFu << shift);
        }
        __syncthreads();
    }

    unsigned T = s_prefix;
    int R = s_rem;   // number of elements equal to T to take (>=1)
    int* tie = g_tie + b * HW;

    for (int i = tid; i < HW; i += 1024) {
        unsigned k = fkey(u[i]);
        if (k > T) {
            int p = atomicAdd(&cSel, 1);
            g_idx[b * NPTS + p] = i;
        } else if (k == T) {
            int p = atomicAdd(&cTie, 1);
            tie[p] = i;
        }
    }
    __syncthreads();
    int E = cTie, base = cSel;   // base + R == NPTS by radix-select invariant
    for (int t = tid; t < E; t += 1024) {
        int my = tie[t];
        int r = 0;
        for (int j = 0; j < E; j++) r += (tie[j] < my) ? 1 : 0;
        if (r < R) g_idx[b * NPTS + base + r] = my;
    }
}

// ---------------------------------------------------------------------------
// Kernel C: per-point feature gather (single-tap: coords round-trip to exact
// pixels), 3-layer MLP with packed f32x2 FMA, scatter into out.
// grid: B * (NPTS/PPB) blocks, 256 threads. Dynamic smem.
// ---------------------------------------------------------------------------
constexpr int SMEM_FLOATS = CIN1 * PPB + HID * PPB;   // pf + h1
constexpr size_t MLP_SMEM = SMEM_FLOATS * sizeof(float) + PPB * sizeof(int);

__global__ void __launch_bounds__(256) mlp_kernel(
    const float* __restrict__ fine,
    const float* __restrict__ w1, const float* __restrict__ b1,
    const float* __restrict__ w2, const float* __restrict__ b2,
    const float* __restrict__ w3, const float* __restrict__ b3,
    float* __restrict__ out)
{
    extern __shared__ float smem[];
    float* pf  = smem;                  // [CIN1][PPB], later reused as h2 [HID][PPB]
    float* h1s = smem + CIN1 * PPB;     // [HID][PPB]
    int*  sidx = (int*)(h1s + HID * PPB);

    int tid = threadIdx.x;
    int b = blockIdx.x >> 6;                       // / BLKS_PER_BATCH
    int pbase = (blockIdx.x & (BLKS_PER_BATCH - 1)) * PPB;

    if (tid < PPB) sidx[tid] = g_idx[b * NPTS + pbase + tid];
    __syncthreads();

    // gather fine features: thread = channel
    {
        const float* fb = fine + (size_t)b * CF * HW + (size_t)tid * HW;
#pragma unroll 8
        for (int p = 0; p < PPB; p++) pf[tid * PPB + p] = fb[sidx[p]];
    }
    // gather coarse_up (already in out)
    if (tid < NC * 8) {
        int c = tid >> 3;
        int p0 = (tid & 7) * 4;
        const float* ob = out + (size_t)(b * NC + c) * HW;
#pragma unroll
        for (int q = 0; q < 4; q++) pf[(CF + c) * PPB + p0 + q] = ob[sidx[p0 + q]];
    }
    __syncthreads();

    int og = tid & 63;      // output group: outputs 4*og .. 4*og+3
    int pg = tid >> 6;      // point group: points 8*pg .. 8*pg+7
    int o0 = og * 4;
    int poff = pg * 8;

    ull acc[16];
    // ---- layer 1: [HID, CIN1] ----
#pragma unroll
    for (int i = 0; i < 16; i++) acc[i] = 0ull;
#pragma unroll 4
    for (int c = 0; c < CIN1; c++) {
        float wv0 = w1[(o0 + 0) * CIN1 + c];
        float wv1 = w1[(o0 + 1) * CIN1 + c];
        float wv2 = w1[(o0 + 2) * CIN1 + c];
        float wv3 = w1[(o0 + 3) * CIN1 + c];
        const ull* row = (const ull*)&pf[c * PPB + poff];
        ull d0 = row[0], d1 = row[1], d2 = row[2], d3 = row[3];
        ull p0 = pack2(wv0), p1 = pack2(wv1), p2 = pack2(wv2), p3 = pack2(wv3);
        acc[0]  = fma2(p0, d0, acc[0]);  acc[1]  = fma2(p0, d1, acc[1]);
        acc[2]  = fma2(p0, d2, acc[2]);  acc[3]  = fma2(p0, d3, acc[3]);
        acc[4]  = fma2(p1, d0, acc[4]);  acc[5]  = fma2(p1, d1, acc[5]);
        acc[6]  = fma2(p1, d2, acc[6]);  acc[7]  = fma2(p1, d3, acc[7]);
        acc[8]  = fma2(p2, d0, acc[8]);  acc[9]  = fma2(p2, d1, acc[9]);
        acc[10] = fma2(p2, d2, acc[10]); acc[11] = fma2(p2, d3, acc[11]);
        acc[12] = fma2(p3, d0, acc[12]); acc[13] = fma2(p3, d1, acc[13]);
        acc[14] = fma2(p3, d2, acc[14]); acc[15] = fma2(p3, d3, acc[15]);
    }
#pragma unroll
    for (int k = 0; k < 4; k++) {
        float bk = b1[o0 + k];
#pragma unroll
        for (int j = 0; j < 4; j++) {
            float x, y;
            unpack2(acc[k * 4 + j], x, y);
            x = fmaxf(x + bk, 0.f);
            y = fmaxf(y + bk, 0.f);
            h1s[(o0 + k) * PPB + poff + 2 * j]     = x;
            h1s[(o0 + k) * PPB + poff + 2 * j + 1] = y;
        }
    }
    __syncthreads();

    // ---- layer 2: [HID, HID], h1s -> pf (reuse) ----
#pragma unroll
    for (int i = 0; i < 16; i++) acc[i] = 0ull;
#pragma unroll 4
    for (int c = 0; c < HID; c++) {
        float wv0 = w2[(o0 + 0) * HID + c];
        float wv1 = w2[(o0 + 1) * HID + c];
        float wv2 = w2[(o0 + 2) * HID + c];
        float wv3 = w2[(o0 + 3) * HID + c];
        const ull* row = (const ull*)&h1s[c * PPB + poff];
        ull d0 = row[0], d1 = row[1], d2 = row[2], d3 = row[3];
        ull p0 = pack2(wv0), p1 = pack2(wv1), p2 = pack2(wv2), p3 = pack2(wv3);
        acc[0]  = fma2(p0, d0, acc[0]);  acc[1]  = fma2(p0, d1, acc[1]);
        acc[2]  = fma2(p0, d2, acc[2]);  acc[3]  = fma2(p0, d3, acc[3]);
        acc[4]  = fma2(p1, d0, acc[4]);  acc[5]  = fma2(p1, d1, acc[5]);
        acc[6]  = fma2(p1, d2, acc[6]);  acc[7]  = fma2(p1, d3, acc[7]);
        acc[8]  = fma2(p2, d0, acc[8]);  acc[9]  = fma2(p2, d1, acc[9]);
        acc[10] = fma2(p2, d2, acc[10]); acc[11] = fma2(p2, d3, acc[11]);
        acc[12] = fma2(p3, d0, acc[12]); acc[13] = fma2(p3, d1, acc[13]);
        acc[14] = fma2(p3, d2, acc[14]); acc[15] = fma2(p3, d3, acc[15]);
    }
    __syncthreads();   // everyone done reading h1s... and pf (dead), safe to overwrite pf
#pragma unroll
    for (int k = 0; k < 4; k++) {
        float bk = b2[o0 + k];
#pragma unroll
        for (int j = 0; j < 4; j++) {
            float x, y;
            unpack2(acc[k * 4 + j], x, y);
            x = fmaxf(x + bk, 0.f);
            y = fmaxf(y + bk, 0.f);
            pf[(o0 + k) * PPB + poff + 2 * j]     = x;
            pf[(o0 + k) * PPB + poff + 2 * j + 1] = y;
        }
    }
    __syncthreads();

    // ---- layer 3: [NC, HID] + scatter ----
    for (int t = tid; t < NC * PPB; t += 256) {
        int o = t >> 5;       // PPB = 32
        int p = t & 31;
        float a = b3[o];
        const float* wr = w3 + o * HID;
#pragma unroll 8
        for (int c = 0; c < HID; c++) a = fmaf(wr[c], pf[c * PPB + p], a);
        out[(size_t)(b * NC + o) * HW + sidx[p]] = a;
    }
}

// ---------------------------------------------------------------------------
extern "C" void kernel_launch(void* const* d_in, const int* in_sizes, int n_in,
                              void* d_out, int out_size)
{
    (void)in_sizes; (void)n_in; (void)out_size;
    const float* coarse = (const float*)d_in[0];
    const float* fine   = (const float*)d_in[1];
    const float* w1     = (const float*)d_in[2];
    const float* b1     = (const float*)d_in[3];
    const float* w2     = (const float*)d_in[4];
    const float* b2     = (const float*)d_in[5];
    const float* w3     = (const float*)d_in[6];
    const float* b3     = (const float*)d_in[7];
    // d_in[8] = num_points (device scalar) — fixed at 2048 by the dataset.
    float* out = (float*)d_out;

    float* unc;
    int dummy_sz;
    (void)dummy_sz;
    cudaGetSymbolAddress((void**)&unc, g_unc);

    static bool attr_done = false;
    if (!attr_done) {
        cudaFuncSetAttribute(mlp_kernel,
                             cudaFuncAttributeMaxDynamicSharedMemorySize,
                             (int)MLP_SMEM);
        attr_done = true;
    }

    upsample_unc_kernel<<<B * HF, WF>>>(coarse, out, unc);
    topk_kernel<<<B, 1024>>>();
    mlp_kernel<<<B * BLKS_PER_BATCH, 256, MLP_SMEM>>>(fine, w1, b1, w2, b2, w3, b3, out);
}

// round 2
// speedup vs baseline: 6.0162x; 6.0162x over previous
#include <cuda_runtime.h>
#include <cstdint>

typedef unsigned long long ull;

// Problem dims (fixed by the dataset's setup_inputs)
constexpr int B   = 8;
constexpr int NC  = 19;
constexpr int HC  = 32;
constexpr int WC  = 64;
constexpr int CF  = 256;
constexpr int HF  = 128;
constexpr int WF  = 256;
constexpr int HID = 256;
constexpr int HW  = HF * WF;         // 32768
constexpr int NPTS = 2048;           // min(2048, HW/4)
constexpr int CIN1 = CF + NC;        // 275
constexpr int PPB  = 32;             // points per block in MLP kernel
constexpr int BLKS_PER_BATCH = NPTS / PPB;  // 64
constexpr int KC   = 32;             // K-chunk for weight tiles
constexpr int OSTR = 260;            // padded out-stride of weight tile (words)

// Scratch (static device memory — no allocation)
__device__ float g_unc[B * HW];
__device__ int   g_idx[B * NPTS];
__device__ int   g_tie[B * HW];

// ---------------------------------------------------------------------------
// f32x2 packed helpers
// ---------------------------------------------------------------------------
__device__ __forceinline__ ull fma2(ull a, ull b, ull c) {
    ull d;
    asm("fma.rn.f32x2 %0, %1, %2, %3;" : "=l"(d) : "l"(a), "l"(b), "l"(c));
    return d;
}
__device__ __forceinline__ ull pack2(float x) {
    ull r;
    asm("mov.b64 %0, {%1, %1};" : "=l"(r) : "f"(x));
    return r;
}
__device__ __forceinline__ void unpack2(ull v, float& x, float& y) {
    asm("mov.b64 {%0, %1}, %2;" : "=f"(x), "=f"(y) : "l"(v));
}

// ---------------------------------------------------------------------------
// Kernel A: bilinear upsample (align_corners) + uncertainty
// ---------------------------------------------------------------------------
__global__ void __launch_bounds__(WF) upsample_unc_kernel(
    const float* __restrict__ coarse, float* __restrict__ out,
    float* __restrict__ unc)
{
    int w = threadIdx.x;
    int h = blockIdx.x % HF;
    int b = blockIdx.x / HF;

    float yf = (float)h * ((float)(HC - 1) / (float)(HF - 1));
    float xf = (float)w * ((float)(WC - 1) / (float)(WF - 1));
    int y0 = (int)floorf(yf); y0 = max(0, min(y0, HC - 1));
    int y1 = min(y0 + 1, HC - 1);
    float wy = yf - (float)y0;
    int x0 = (int)floorf(xf); x0 = max(0, min(x0, WC - 1));
    int x1 = min(x0 + 1, WC - 1);
    float wx = xf - (float)x0;

    const float* cb = coarse + (size_t)b * NC * HC * WC;
    float v[NC];
    float vmax = -3.4e38f;
#pragma unroll
    for (int c = 0; c < NC; c++) {
        const float* p = cb + c * HC * WC;
        float c00 = p[y0 * WC + x0], c10 = p[y1 * WC + x0];
        float c01 = p[y0 * WC + x1], c11 = p[y1 * WC + x1];
        float r0 = c00 * (1.f - wy) + c10 * wy;
        float r1 = c01 * (1.f - wy) + c11 * wy;
        float val = r0 * (1.f - wx) + r1 * wx;
        v[c] = val;
        vmax = fmaxf(vmax, val);
        out[((size_t)(b * NC + c) * HF + h) * WF + w] = val;
    }
    float s = 0.f;
#pragma unroll
    for (int c = 0; c < NC; c++) s += expf(v[c] - vmax);
    unc[b * HW + h * WF + w] = -1.0f / s;
}

// ---------------------------------------------------------------------------
// Kernel B: exact top-NPTS per batch via 4x8-bit radix select.
// ---------------------------------------------------------------------------
__device__ __forceinline__ unsigned fkey(float f) {
    unsigned u = __float_as_uint(f);
    return (u & 0x80000000u) ? ~u : (u | 0x80000000u);
}

__global__ void __launch_bounds__(1024) topk_kernel() {
    int b = blockIdx.x;
    int tid = threadIdx.x;
    const float* u = g_unc + b * HW;

    __shared__ unsigned hist[256];
    __shared__ unsigned s_prefix;
    __shared__ unsigned s_mask;
    __shared__ int s_rem;
    __shared__ int cSel, cTie;

    if (tid == 0) { s_prefix = 0; s_mask = 0; s_rem = NPTS; cSel = 0; cTie = 0; }
    __syncthreads();

    for (int pass = 0; pass < 4; pass++) {
        int shift = (3 - pass) * 8;
        if (tid < 256) hist[tid] = 0;
        __syncthreads();
        unsigned mask = s_mask, pref = s_prefix;
        for (int i = tid; i < HW; i += 1024) {
            unsigned k = fkey(u[i]);
            if ((k & mask) == pref) atomicAdd(&hist[(k >> shift) & 255], 1u);
        }
        __syncthreads();
        if (tid == 0) {
            int need = s_rem;
            unsigned cum = 0;
            int sel = 0;
            for (int bin = 255; bin >= 0; bin--) {
                unsigned h = hist[bin];
                if (cum + h >= (unsigned)need) { sel = bin; s_rem = need - (int)cum; break; }
                cum += h;
            }
            s_prefix = pref | ((unsigned)sel << shift);
            s_mask = mask | (0xFFu << shift);
        }
        __syncthreads();
    }

    unsigned T = s_prefix;
    int R = s_rem;
    int* tie = g_tie + b * HW;

    for (int i = tid; i < HW; i += 1024) {
        unsigned k = fkey(u[i]);
        if (k > T) {
            int p = atomicAdd(&cSel, 1);
            g_idx[b * NPTS + p] = i;
        } else if (k == T) {
            int p = atomicAdd(&cTie, 1);
            tie[p] = i;
        }
    }
    __syncthreads();
    int E = cTie, base = cSel;
    for (int t = tid; t < E; t += 1024) {
        int my = tie[t];
        int r = 0;
        for (int j = 0; j < E; j++) r += (tie[j] < my) ? 1 : 0;
        if (r < R) g_idx[b * NPTS + base + r] = my;
    }
}

// ---------------------------------------------------------------------------
// Kernel C: gather + 3-layer MLP (smem-staged weight tiles, f32x2 FMA) + scatter
// ---------------------------------------------------------------------------
constexpr int WT_FLOATS = KC * OSTR;                              // 8320
constexpr int SMEM_FLOATS = CIN1 * PPB + HID * PPB + WT_FLOATS;   // 25312
constexpr size_t MLP_SMEM = SMEM_FLOATS * sizeof(float) + PPB * sizeof(int);

// Cooperative coalesced load of a KCxHID weight tile, transposed into wt[k][o]
// (padded stride OSTR). Lanes within a warp read consecutive c -> 128B lines.
__device__ __forceinline__ void load_wtile(
    const float* __restrict__ W, int CIN, int c0, int kc, float* wt, int tid)
{
    int k = tid & 31;        // k within chunk
    int ob = tid >> 5;       // 0..7
    bool valid = (k < kc);
#pragma unroll
    for (int i = 0; i < 32; i++) {
        int o = i * 8 + ob;
        float v = valid ? W[o * CIN + c0 + k] : 0.f;
        wt[k * OSTR + o] = v;
    }
}

template <int KCC>
__device__ __forceinline__ void mma_chunk(
    const float* wt, const float* pf, int c0, int o0, int poff, ull* acc)
{
#pragma unroll 8
    for (int c = 0; c < KCC; c++) {
        float4 wv = *reinterpret_cast<const float4*>(&wt[c * OSTR + o0]);
        ull p0 = pack2(wv.x), p1 = pack2(wv.y), p2 = pack2(wv.z), p3 = pack2(wv.w);
        const ull* row = reinterpret_cast<const ull*>(&pf[(c0 + c) * PPB + poff]);
        ull d0 = row[0], d1 = row[1], d2 = row[2], d3 = row[3];
        acc[0]  = fma2(p0, d0, acc[0]);  acc[1]  = fma2(p0, d1, acc[1]);
        acc[2]  = fma2(p0, d2, acc[2]);  acc[3]  = fma2(p0, d3, acc[3]);
        acc[4]  = fma2(p1, d0, acc[4]);  acc[5]  = fma2(p1, d1, acc[5]);
        acc[6]  = fma2(p1, d2, acc[6]);  acc[7]  = fma2(p1, d3, acc[7]);
        acc[8]  = fma2(p2, d0, acc[8]);  acc[9]  = fma2(p2, d1, acc[9]);
        acc[10] = fma2(p2, d2, acc[10]); acc[11] = fma2(p2, d3, acc[11]);
        acc[12] = fma2(p3, d0, acc[12]); acc[13] = fma2(p3, d1, acc[13]);
        acc[14] = fma2(p3, d2, acc[14]); acc[15] = fma2(p3, d3, acc[15]);
    }
}

__global__ void __launch_bounds__(256) mlp_kernel(
    const float* __restrict__ fine,
    const float* __restrict__ w1, const float* __restrict__ b1,
    const float* __restrict__ w2, const float* __restrict__ b2,
    const float* __restrict__ w3, const float* __restrict__ b3,
    float* __restrict__ out)
{
    extern __shared__ float smem[];
    float* pf  = smem;                      // [CIN1][PPB]; reused as h2 [HID][PPB]
    float* h1s = pf + CIN1 * PPB;           // [HID][PPB]
    float* wt  = h1s + HID * PPB;           // [KC][OSTR]
    int*  sidx = (int*)(wt + WT_FLOATS);

    int tid = threadIdx.x;
    int b = blockIdx.x >> 6;                       // / BLKS_PER_BATCH
    int pbase = (blockIdx.x & (BLKS_PER_BATCH - 1)) * PPB;

    if (tid < PPB) sidx[tid] = g_idx[b * NPTS + pbase + tid];
    __syncthreads();

    // gather fine features: thread = channel (inherently scattered gather)
    {
        const float* fb = fine + (size_t)b * CF * HW + (size_t)tid * HW;
#pragma unroll 8
        for (int p = 0; p < PPB; p++) pf[tid * PPB + p] = fb[sidx[p]];
    }
    // gather coarse_up (already in out)
    if (tid < NC * 8) {
        int c = tid >> 3;
        int p0 = (tid & 7) * 4;
        const float* ob = out + (size_t)(b * NC + c) * HW;
#pragma unroll
        for (int q = 0; q < 4; q++) pf[(CF + c) * PPB + p0 + q] = ob[sidx[p0 + q]];
    }

    int og = tid & 63;      // output group: outputs 4*og .. 4*og+3
    int pg = tid >> 6;      // point group: points 8*pg .. 8*pg+7
    int o0 = og * 4;
    int poff = pg * 8;

    ull acc[16];

    // ---- layer 1: [HID, CIN1] = 8 full chunks + 19 remainder ----
#pragma unroll
    for (int i = 0; i < 16; i++) acc[i] = 0ull;
    for (int ch = 0; ch < 8; ch++) {
        __syncthreads();                        // prev consumers done / pf ready
        load_wtile(w1, CIN1, ch * KC, KC, wt, tid);
        __syncthreads();
        mma_chunk<KC>(wt, pf, ch * KC, o0, poff, acc);
    }
    __syncthreads();
    load_wtile(w1, CIN1, 8 * KC, CIN1 - 8 * KC, wt, tid);
    __syncthreads();
    mma_chunk<CIN1 - 8 * KC>(wt, pf, 8 * KC, o0, poff, acc);

#pragma unroll
    for (int k = 0; k < 4; k++) {
        float bk = b1[o0 + k];
#pragma unroll
        for (int j = 0; j < 4; j++) {
            float x, y;
            unpack2(acc[k * 4 + j], x, y);
            x = fmaxf(x + bk, 0.f);
            y = fmaxf(y + bk, 0.f);
            h1s[(o0 + k) * PPB + poff + 2 * j]     = x;
            h1s[(o0 + k) * PPB + poff + 2 * j + 1] = y;
        }
    }

    // ---- layer 2: [HID, HID] = 8 full chunks, h1s -> (pf reused as h2) ----
#pragma unroll
    for (int i = 0; i < 16; i++) acc[i] = 0ull;
    for (int ch = 0; ch < 8; ch++) {
        __syncthreads();
        load_wtile(w2, HID, ch * KC, KC, wt, tid);
        __syncthreads();
        mma_chunk<KC>(wt, h1s, ch * KC, o0, poff, acc);
    }
    __syncthreads();   // all reads of pf (layer1 data) long done; safe to overwrite
#pragma unroll
    for (int k = 0; k < 4; k++) {
        float bk = b2[o0 + k];
#pragma unroll
        for (int j = 0; j < 4; j++) {
            float x, y;
            unpack2(acc[k * 4 + j], x, y);
            x = fmaxf(x + bk, 0.f);
            y = fmaxf(y + bk, 0.f);
            pf[(o0 + k) * PPB + poff + 2 * j]     = x;
            pf[(o0 + k) * PPB + poff + 2 * j + 1] = y;
        }
    }
    __syncthreads();

    // ---- layer 3: [NC, HID] + scatter (w3 reads are warp-uniform -> bcast) ----
    for (int t = tid; t < NC * PPB; t += 256) {
        int o = t >> 5;       // PPB = 32
        int p = t & 31;
        float a = b3[o];
        const float* wr = w3 + o * HID;
#pragma unroll 8
        for (int c = 0; c < HID; c++) a = fmaf(wr[c], pf[c * PPB + p], a);
        out[(size_t)(b * NC + o) * HW + sidx[p]] = a;
    }
}

// ---------------------------------------------------------------------------
extern "C" void kernel_launch(void* const* d_in, const int* in_sizes, int n_in,
                              void* d_out, int out_size)
{
    (void)in_sizes; (void)n_in; (void)out_size;
    const float* coarse = (const float*)d_in[0];
    const float* fine   = (const float*)d_in[1];
    const float* w1     = (const float*)d_in[2];
    const float* b1     = (const float*)d_in[3];
    const float* w2     = (const float*)d_in[4];
    const float* b2     = (const float*)d_in[5];
    const float* w3     = (const float*)d_in[6];
    const float* b3     = (const float*)d_in[7];
    float* out = (float*)d_out;

    static float* unc = nullptr;
    if (!unc) cudaGetSymbolAddress((void**)&unc, g_unc);

    static bool attr_done = false;
    if (!attr_done) {
        cudaFuncSetAttribute(mlp_kernel,
                             cudaFuncAttributeMaxDynamicSharedMemorySize,
                             (int)MLP_SMEM);
        attr_done = true;
    }

    upsample_unc_kernel<<<B * HF, WF>>>(coarse, out, unc);
    topk_kernel<<<B, 1024>>>();
    mlp_kernel<<<B * BLKS_PER_BATCH, 256, MLP_SMEM>>>(fine, w1, b1, w2, b2, w3, b3, out);
}